// round 4
// baseline (speedup 1.0000x reference)
#include <cuda_runtime.h>
#include <cstdint>
#include <math.h>

#define KSEL 100
#define NTHREADS 256
#define CAND_MAX 512
#define SAMPLE_NUM 10

__global__ __launch_bounds__(NTHREADS) void postprocess_kernel(
    const float* __restrict__ blk_logits,
    const float* __restrict__ lin_logits,
    const float* __restrict__ chr_logits,
    const float* __restrict__ blk_raw,
    const float* __restrict__ lin_raw,
    const float* __restrict__ chr_raw,
    const float* __restrict__ tsizes,
    float* __restrict__ out)
{
    extern __shared__ uint32_t sKeys[];          // up to 16384 keys
    __shared__ int       sHist[256];
    __shared__ unsigned long long sCand[CAND_MAX];
    __shared__ int       sCnt;
    __shared__ uint32_t  sPrefix;
    __shared__ int       sRemaining;
    __shared__ float     sVal[KSEL];
    __shared__ int       sIdx[KSEL];
    __shared__ float     sData[KSEL * 16];
    __shared__ float     sBox[KSEL * 4];
    __shared__ float     sArea[KSEL];
    __shared__ int       sKeep[KSEL];
    __shared__ float     sBelong[KSEL];
    __shared__ int       sFlag;
    __shared__ int       sFb;

    const int b     = blockIdx.x;
    const int level = blockIdx.y;
    const int tid   = threadIdx.x;

    const float* logits;
    const float* raw;
    const float* parent = nullptr;
    int N, parentN = 0, ef = 1;
    bool bez = false;
    int data_off, score_off, keep_off, dd;

    if (level == 0) {
        logits = blk_logits; raw = blk_raw; N = 4096; dd = 4;
        data_off = 0;      score_off = 25600;  keep_off = 32000;
    } else if (level == 1) {
        logits = lin_logits; raw = lin_raw; parent = blk_raw; parentN = 4096; ef = 4;
        N = 16384; dd = 4;
        data_off = 38400;  score_off = 64000;  keep_off = 70400;
    } else {
        logits = chr_logits; raw = chr_raw; parent = lin_raw; parentN = 16384; ef = 1;
        N = 16384; dd = 16; bez = true;
        data_off = 76800;  score_off = 179200; keep_off = 185600;
    }

    const float img_h = tsizes[2 * b + 0];
    const float img_w = tsizes[2 * b + 1];

    // ---- 1. build sortable keys in shared ----
    const float* lg = logits + (size_t)b * N;
    for (int i = tid; i < N; i += NTHREADS) {
        uint32_t u = __float_as_uint(lg[i]);
        sKeys[i] = (u & 0x80000000u) ? ~u : (u | 0x80000000u);
    }
    if (tid == 0) { sRemaining = KSEL; sPrefix = 0u; sCnt = 0; }
    __syncthreads();

    // ---- 2. 4-pass radix select: find value of 100th-largest key ----
    #pragma unroll
    for (int pass = 0; pass < 4; pass++) {
        const int shift = 24 - 8 * pass;
        const uint32_t hi_mask = (pass == 0) ? 0u : (0xFFFFFFFFu << (shift + 8));
        sHist[tid] = 0;
        __syncthreads();
        const uint32_t pref = sPrefix;
        for (int i = tid; i < N; i += NTHREADS) {
            uint32_t kk = sKeys[i];
            if ((kk & hi_mask) == pref)
                atomicAdd(&sHist[(kk >> shift) & 0xFF], 1);
        }
        __syncthreads();
        // suffix sums (Hillis-Steele): sHist[t] := count of keys in bins >= t
        for (int d = 1; d < 256; d <<= 1) {
            int v = (tid + d < 256) ? sHist[tid + d] : 0;
            __syncthreads();
            sHist[tid] += v;
            __syncthreads();
        }
        const int rem = sRemaining;
        {
            int s_here = sHist[tid];
            int s_next = (tid < 255) ? sHist[tid + 1] : 0;
            if (s_here >= rem && s_next < rem) {
                sPrefix = pref | ((uint32_t)tid << shift);
                sRemaining = rem - s_next;
            }
        }
        __syncthreads();
    }

    const uint32_t T = sPrefix;

    // ---- 3. collect candidates >= T ----
    for (int i = tid; i < N; i += NTHREADS) {
        uint32_t kk = sKeys[i];
        if (kk >= T) {
            int pos = atomicAdd(&sCnt, 1);
            if (pos < CAND_MAX) {
                unsigned long long comb =
                    ((unsigned long long)kk << 32) |
                    (unsigned long long)(0xFFFFFFFFu - (uint32_t)i);
                sCand[pos] = ~comb;   // sort ascending on ~comb -> key desc, idx asc
            }
        }
    }
    __syncthreads();
    const int cnt = min(sCnt, CAND_MAX);
    for (int i = cnt + tid; i < CAND_MAX; i += NTHREADS)
        sCand[i] = 0xFFFFFFFFFFFFFFFFull;   // sorts last
    __syncthreads();

    // ---- bitonic sort 512 elements with 256 threads, ascending ----
    for (int size2 = 2; size2 <= CAND_MAX; size2 <<= 1) {
        for (int stride = size2 >> 1; stride > 0; stride >>= 1) {
            __syncthreads();
            int pos = ((tid & ~(stride - 1)) << 1) | (tid & (stride - 1));
            bool up = ((pos & size2) == 0);
            unsigned long long a = sCand[pos];
            unsigned long long c = sCand[pos + stride];
            if ((a > c) == up) { sCand[pos] = c; sCand[pos + stride] = a; }
        }
    }
    __syncthreads();

    // ---- 4. decode top-100, compute values ----
    if (tid < KSEL) {
        unsigned long long comb = ~sCand[tid];
        uint32_t kk  = (uint32_t)(comb >> 32);
        uint32_t idx = 0xFFFFFFFFu - (uint32_t)(comb & 0xFFFFFFFFull);
        sIdx[tid] = (int)idx;
        uint32_t u = (kk & 0x80000000u) ? (kk & 0x7FFFFFFFu) : ~kk;
        float lv = __uint_as_float(u);
        sVal[tid] = 1.0f / (1.0f + expf(-lv));
    }
    __syncthreads();

    // ---- 5. boxes / data ----
    if (tid < KSEL) {
        int si = sIdx[tid];
        if (!bez) {
            const float* r = raw + ((size_t)b * N + si) * 4;
            float cx = r[0], cy = r[1], w = r[2], h = r[3];
            float x1 = (cx - 0.5f * w) * img_w;
            float y1 = (cy - 0.5f * h) * img_h;
            float x2 = (cx + 0.5f * w) * img_w;
            float y2 = (cy + 0.5f * h) * img_h;
            if (level == 0) {  // clip only when no parent
                x1 = fminf(fmaxf(x1, 0.0f), img_w);
                y1 = fminf(fmaxf(y1, 0.0f), img_h);
                x2 = fminf(fmaxf(x2, 0.0f), img_w);
                y2 = fminf(fmaxf(y2, 0.0f), img_h);
            }
            sData[tid * 16 + 0] = x1; sData[tid * 16 + 1] = y1;
            sData[tid * 16 + 2] = x2; sData[tid * 16 + 3] = y2;
            sBox[tid * 4 + 0] = x1; sBox[tid * 4 + 1] = y1;
            sBox[tid * 4 + 2] = x2; sBox[tid * 4 + 3] = y2;
        } else {
            const float* r = raw + ((size_t)b * N + si) * 16;
            float cp0[8], cp1[8];
            #pragma unroll
            for (int f = 0; f < 8; f++) {
                cp0[f] = r[2 * f + 0] * img_h;   // scale_pts = tile((h,w),8)
                cp1[f] = r[2 * f + 1] * img_w;
                sData[tid * 16 + 2 * f + 0] = cp0[f];
                sData[tid * 16 + 2 * f + 1] = cp1[f];
            }
            float mn0 =  INFINITY, mn1 =  INFINITY;
            float mx0 = -INFINITY, mx1 = -INFINITY;
            #pragma unroll
            for (int s = 0; s < SAMPLE_NUM; s++) {
                float t  = (float)s / (float)(SAMPLE_NUM - 1);
                float ti = 1.0f - t;
                float b0 = ti * ti * ti;
                float b1 = 3.0f * t * ti * ti;
                float b2 = 3.0f * t * t * ti;
                float b3 = t * t * t;
                float px = b0 * cp0[0] + b1 * cp0[1] + b2 * cp0[2] + b3 * cp0[3];
                float py = b0 * cp1[0] + b1 * cp1[1] + b2 * cp1[2] + b3 * cp1[3];
                float qx = b0 * cp0[4] + b1 * cp0[5] + b2 * cp0[6] + b3 * cp0[7];
                float qy = b0 * cp1[4] + b1 * cp1[5] + b2 * cp1[6] + b3 * cp1[7];
                mn0 = fminf(mn0, fminf(px, qx));
                mn1 = fminf(mn1, fminf(py, qy));
                mx0 = fmaxf(mx0, fmaxf(px, qx));
                mx1 = fmaxf(mx1, fmaxf(py, qy));
            }
            sBox[tid * 4 + 0] = mn0; sBox[tid * 4 + 1] = mn1;
            sBox[tid * 4 + 2] = mx0; sBox[tid * 4 + 3] = mx1;
        }
    }

    // ---- 6. keep = vals > 0.1 (with fallback to index 0) ----
    if (tid == 0) sFlag = 0;
    __syncthreads();
    int keep0 = 0;
    if (tid < KSEL) {
        keep0 = (sVal[tid] > 0.1f) ? 1 : 0;
        if (keep0) atomicOr(&sFlag, 1);
    }
    __syncthreads();
    const int any0 = sFlag;
    if (tid < KSEL) sKeep[tid] = any0 ? keep0 : (tid == 0 ? 1 : 0);
    __syncthreads();

    // ---- 7. parent belong filter (line / char) ----
    if (level > 0) {
        if (tid == 0) sFlag = 0;
        __syncthreads();
        int valid = 0;
        if (tid < KSEL) {
            int pi = sIdx[tid] / ef;
            const float* pr = parent + ((size_t)b * parentN + pi) * 4;
            float pcx = pr[0], pcy = pr[1], pw = pr[2], ph = pr[3];
            float px1 = (pcx - 0.5f * pw) * img_w;
            float py1 = (pcy - 0.5f * ph) * img_h;
            float px2 = (pcx + 0.5f * pw) * img_w;
            float py2 = (pcy + 0.5f * ph) * img_h;
            float bx1 = sBox[tid * 4 + 0], by1 = sBox[tid * 4 + 1];
            float bx2 = sBox[tid * 4 + 2], by2 = sBox[tid * 4 + 3];
            float ix1 = fmaxf(bx1, px1), iy1 = fmaxf(by1, py1);
            float ix2 = fminf(bx2, px2), iy2 = fminf(by2, py2);
            float inter = fmaxf(ix2 - ix1, 0.0f) * fmaxf(iy2 - iy1, 0.0f);
            float carea = (bx2 - bx1) * (by2 - by1);
            float belong = inter / (carea + 1e-6f);
            sBelong[tid] = belong;
            valid = (belong > 0.6f) ? 1 : 0;
            if (valid && sKeep[tid]) atomicOr(&sFlag, 1);
        }
        __syncthreads();
        const int haveValid = sFlag;
        if (!haveValid) {
            if (tid == 0) {
                float best = -INFINITY; int bi = 0;
                for (int kk = 0; kk < KSEL; kk++) {
                    float v = sKeep[kk] ? sBelong[kk] : -INFINITY;
                    if (v > best) { best = v; bi = kk; }
                }
                sFb = bi;
            }
            __syncthreads();
            if (tid < KSEL) valid = (tid == sFb) ? 1 : 0;
        }
        if (tid < KSEL) sKeep[tid] = sKeep[tid] & valid;
        __syncthreads();
    }

    // ---- 8. greedy NMS over K=100 ----
    if (tid < KSEL)
        sArea[tid] = (sBox[tid * 4 + 2] - sBox[tid * 4 + 0]) *
                     (sBox[tid * 4 + 3] - sBox[tid * 4 + 1]);
    __syncthreads();
    for (int i = 0; i < KSEL; i++) {
        int ki = sKeep[i];
        if (ki && tid < KSEL && tid > i && sKeep[tid]) {
            float ix1 = fmaxf(sBox[i * 4 + 0], sBox[tid * 4 + 0]);
            float iy1 = fmaxf(sBox[i * 4 + 1], sBox[tid * 4 + 1]);
            float ix2 = fminf(sBox[i * 4 + 2], sBox[tid * 4 + 2]);
            float iy2 = fminf(sBox[i * 4 + 3], sBox[tid * 4 + 3]);
            float inter = fmaxf(ix2 - ix1, 0.0f) * fmaxf(iy2 - iy1, 0.0f);
            float iou = inter / (sArea[i] + sArea[tid] - inter);
            if (iou > 0.1f) sKeep[tid] = 0;
        }
        __syncthreads();
    }

    // ---- 9. write outputs (float32; keep as 0/1) ----
    if (tid < KSEL) {
        const int nk = sKeep[tid];
        for (int j = 0; j < dd; j++)
            out[data_off + ((size_t)b * KSEL + tid) * dd + j] =
                nk ? sData[tid * 16 + j] : 0.0f;
        out[score_off + (size_t)b * KSEL + tid] = nk ? sVal[tid] : 0.0f;
        out[keep_off  + (size_t)b * KSEL + tid] = nk ? 1.0f : 0.0f;
    }
}

extern "C" void kernel_launch(void* const* d_in, const int* in_sizes, int n_in,
                              void* d_out, int out_size) {
    const float* blk_logits = (const float*)d_in[0];
    const float* lin_logits = (const float*)d_in[1];
    const float* chr_logits = (const float*)d_in[2];
    const float* blk_raw    = (const float*)d_in[3];
    const float* lin_raw    = (const float*)d_in[4];
    const float* chr_raw    = (const float*)d_in[5];
    const float* tsizes     = (const float*)d_in[6];
    float* out = (float*)d_out;

    const int smem = 16384 * sizeof(uint32_t);
    cudaFuncSetAttribute(postprocess_kernel,
                         cudaFuncAttributeMaxDynamicSharedMemorySize, smem);
    dim3 grid(64, 3);
    postprocess_kernel<<<grid, NTHREADS, smem>>>(
        blk_logits, lin_logits, chr_logits,
        blk_raw, lin_raw, chr_raw, tsizes, out);
}